// round 5
// baseline (speedup 1.0000x reference)
#include <cuda_runtime.h>
#include <cuda_fp16.h>
#include <cstdint>

// ---------------------------------------------------------------------------
// Problem constants
// ---------------------------------------------------------------------------
#define BATCH        2048
#define IN_FEAT      4096
#define OUT_FEAT     4096
#define BLOCK        32
#define NNZ          2048
#define N_ROW_BLOCKS 128
#define MTILE        128                    // batch rows per CTA
#define N_BATCH_TILES (BATCH / MTILE)       // 16

// ---------------------------------------------------------------------------
// Device scratch (__device__ globals only; no runtime allocation)
// ---------------------------------------------------------------------------
__device__ __align__(256) __half g_xh[BATCH * IN_FEAT];     // 16 MB
__device__ __align__(256) __half g_wh[NNZ * BLOCK * BLOCK]; // 4 MB
__device__ int g_cnt[N_ROW_BLOCKS];
__device__ int g_off[N_ROW_BLOCKS];
__device__ int g_order[N_ROW_BLOCKS];   // row-blocks sorted by cnt desc
__device__ int g_list[NNZ];             // packed: (col << 16) | nnz_index

// ---------------------------------------------------------------------------
// Helpers
// ---------------------------------------------------------------------------
__device__ __forceinline__ uint32_t smem_u32(const void* p) {
    uint32_t a;
    asm("{ .reg .u64 t; cvta.to.shared.u64 t, %1; cvt.u32.u64 %0, t; }"
        : "=r"(a) : "l"(p));
    return a;
}

// SW128-style swizzle over 128B-pitch rows: XOR bits [6:4] with bits [9:7].
#define SW(o) ((o) ^ (((o) >> 3) & 0x70))

#define CP_ASYNC16(dst, src) \
    asm volatile("cp.async.cg.shared.global [%0], [%1], 16;" \
                 :: "r"(dst), "l"(src) : "memory")
#define CP_COMMIT() asm volatile("cp.async.commit_group;" ::: "memory")
#define CP_WAIT1()  asm volatile("cp.async.wait_group 1;" ::: "memory")
#define CP_WAIT2()  asm volatile("cp.async.wait_group 2;" ::: "memory")

__device__ __forceinline__ void ldsm_x4(uint32_t* r, uint32_t addr) {
    asm volatile("ldmatrix.sync.aligned.m8n8.x4.shared.b16 {%0,%1,%2,%3}, [%4];"
                 : "=r"(r[0]), "=r"(r[1]), "=r"(r[2]), "=r"(r[3])
                 : "r"(addr));
}

__device__ __forceinline__ void mma_16816(float* d, const uint32_t* a,
                                          const uint32_t* b) {
    asm volatile(
        "mma.sync.aligned.m16n8k16.row.col.f32.f16.f16.f32 "
        "{%0,%1,%2,%3}, {%4,%5,%6,%7}, {%8,%9}, {%0,%1,%2,%3};"
        : "+f"(d[0]), "+f"(d[1]), "+f"(d[2]), "+f"(d[3])
        : "r"(a[0]), "r"(a[1]), "r"(a[2]), "r"(a[3]), "r"(b[0]), "r"(b[1]));
}

// ---------------------------------------------------------------------------
// Kernel 1: fused fp32 -> fp16 conversion for x and w.
// x: 2048*4096/4 = 2,097,152 float4 -> 8192 blocks. w: 524,288 -> 2048 blocks.
// ---------------------------------------------------------------------------
#define X_F4_BLOCKS 8192
#define W_F4_BLOCKS 2048

__global__ void __launch_bounds__(256) cvt_kernel(const float* __restrict__ x,
                                                  const float* __restrict__ w) {
    int b = blockIdx.x;
    if (b < X_F4_BLOCKS) {
        int i = b * 256 + threadIdx.x;
        float4 v = reinterpret_cast<const float4*>(x)[i];
        __half2* d = reinterpret_cast<__half2*>(g_xh);
        d[2 * i]     = __floats2half2_rn(v.x, v.y);
        d[2 * i + 1] = __floats2half2_rn(v.z, v.w);
    } else {
        int i = (b - X_F4_BLOCKS) * 256 + threadIdx.x;
        float4 v = reinterpret_cast<const float4*>(w)[i];
        __half2* d = reinterpret_cast<__half2*>(g_wh);
        d[2 * i]     = __floats2half2_rn(v.x, v.y);
        d[2 * i + 1] = __floats2half2_rn(v.z, v.w);
    }
}

// ---------------------------------------------------------------------------
// Kernel 2: fused CSR build (count + prefix + scatter + longest-first order).
// One block, 128 threads; thread r owns row-block r. rows[n] loads are
// uniform across threads -> broadcast L1 hits.
// ---------------------------------------------------------------------------
__global__ void __launch_bounds__(128) csr_build_kernel(const int* __restrict__ rows,
                                                        const int* __restrict__ cols) {
    const int r = threadIdx.x;
    int cnt = 0;
#pragma unroll 8
    for (int n = 0; n < NNZ; n++) cnt += (rows[n] == r);

    __shared__ int s[N_ROW_BLOCKS];
    s[r] = cnt;
    __syncthreads();

    int off = 0, rank = 0;
#pragma unroll 8
    for (int i = 0; i < N_ROW_BLOCKS; i++) {
        int ci = s[i];
        off  += (i < r) ? ci : 0;
        rank += (ci > cnt) || (ci == cnt && i < r);
    }
    g_cnt[r] = cnt;
    g_off[r] = off;
    g_order[rank] = r;

    int pos = off;
    for (int n = 0; n < NNZ; n++) {
        if (rows[n] == r) g_list[pos++] = (cols[n] << 16) | n;
    }
}

// ---------------------------------------------------------------------------
// Kernel 3: main block-sparse GEMM.
// Grid (128 row-blocks via g_order, 16 batch-tiles), 128 threads.
// 3-stage cp.async pipeline, register-double-buffered ldmatrix fragments,
// ONE __syncthreads per mainloop iteration.
// ---------------------------------------------------------------------------
#define A_BYTES     (MTILE * 128)          // 16384 per stage
#define B_BYTES     (BLOCK * 128)          // 4096  per stage
#define STAGE_BYTES (A_BYTES + B_BYTES)    // 20480
#define STAGES      3
#define SMEM_DYN    (STAGES * STAGE_BYTES) // 61440

__device__ __forceinline__ void issue_loads(uint32_t sA, uint32_t sB,
                                            int tid, int batch0, int packed) {
    const int c   = packed >> 16;
    const int idx = packed & 0xffff;
    const char* xs = reinterpret_cast<const char*>(
        g_xh + (size_t)(batch0 + tid) * IN_FEAT + c * BLOCK);
#pragma unroll
    for (int i = 0; i < 4; i++)
        CP_ASYNC16(sA + SW((uint32_t)tid * 128 + i * 16), xs + i * 16);
    const int wr = tid >> 2, wi = tid & 3;
    const char* ws = reinterpret_cast<const char*>(
        g_wh + (size_t)idx * (BLOCK * BLOCK) + wr * BLOCK + wi * 8);
    CP_ASYNC16(sB + SW((uint32_t)wr * 128 + wi * 16), ws);
}

__device__ __forceinline__ void load_frags(uint32_t (&af)[2][2][4],
                                           uint32_t (&bf)[2][4][2],
                                           uint32_t sA, uint32_t sB,
                                           int mbase, int lid) {
#pragma unroll
    for (int mi = 0; mi < 2; mi++)
#pragma unroll
        for (int ki = 0; ki < 2; ki++) {
            uint32_t row = (uint32_t)(mbase + mi * 16 + (lid & 15));
            uint32_t kb  = (uint32_t)(ki * 32 + ((lid >> 4) * 16));
            ldsm_x4(af[mi][ki], sA + SW(row * 128 + kb));
        }
#pragma unroll
    for (int ki = 0; ki < 2; ki++)
#pragma unroll
        for (int p = 0; p < 2; p++) {
            uint32_t n  = (uint32_t)(p * 16 + ((lid >> 4) * 8) + (lid & 7));
            uint32_t kb = (uint32_t)(ki * 32 + (((lid >> 3) & 1) * 16));
            uint32_t t[4];
            ldsm_x4(t, sB + SW(n * 128 + kb));
            bf[ki][2 * p + 0][0] = t[0];
            bf[ki][2 * p + 0][1] = t[1];
            bf[ki][2 * p + 1][0] = t[2];
            bf[ki][2 * p + 1][1] = t[3];
        }
}

__device__ __forceinline__ void do_mmas(float (&acc)[2][4][4],
                                        const uint32_t (&af)[2][2][4],
                                        const uint32_t (&bf)[2][4][2]) {
#pragma unroll
    for (int mi = 0; mi < 2; mi++)
#pragma unroll
        for (int nj = 0; nj < 4; nj++)
#pragma unroll
            for (int ki = 0; ki < 2; ki++)
                mma_16816(acc[mi][nj], af[mi][ki], bf[ki][nj]);
}

__global__ void __launch_bounds__(128)
bsd_main_kernel(float* __restrict__ out) {
    extern __shared__ char sbuf[];

    const int r      = g_order[blockIdx.x];
    const int batch0 = blockIdx.y * MTILE;
    const int tid = threadIdx.x;
    const int wid = tid >> 5;
    const int lid = tid & 31;
    const int mbase = wid * 32;

    const uint32_t sb = smem_u32(sbuf);
    const int cnt = g_cnt[r];
    const int off = g_off[r];

    float acc[2][4][4];
#pragma unroll
    for (int mi = 0; mi < 2; mi++)
#pragma unroll
        for (int nj = 0; nj < 4; nj++)
#pragma unroll
            for (int k = 0; k < 4; k++) acc[mi][nj][k] = 0.f;

    uint32_t af0[2][2][4], bf0[2][4][2];
    uint32_t af1[2][2][4], bf1[2][4][2];

    // Prologue: fill 3 stages (commit always, to keep group numbering fixed)
#pragma unroll
    for (int s = 0; s < STAGES; s++) {
        if (s < cnt)
            issue_loads(sb + s * STAGE_BYTES, sb + s * STAGE_BYTES + A_BYTES,
                        tid, batch0, g_list[off + s]);
        CP_COMMIT();
    }
    CP_WAIT2();            // stage 0 complete
    __syncthreads();       // visible to all threads
    if (cnt > 0)
        load_frags(af0, bf0, sb, sb + A_BYTES, mbase, lid);

    // Mainloop: one barrier per iteration.
    //  - wait_group(1): buffer for it+1 complete (groups issued through it+2)
    //  - sync: (a) visibility of stage (it+1)%3, (b) all threads done reading
    //          stage it%3 (their ldmatrix of it happened before this sync)
    //  - refill stage it%3 with block it+3
    //  - prefetch frags for it+1, then MMA for it
    for (int it = 0; it < cnt; ++it) {
        CP_WAIT1();
        __syncthreads();

        const int stage_w = it % STAGES;                    // refill target
        const int j = it + STAGES;
        if (j < cnt)
            issue_loads(sb + stage_w * STAGE_BYTES,
                        sb + stage_w * STAGE_BYTES + A_BYTES,
                        tid, batch0, g_list[off + j]);
        CP_COMMIT();

        const int stage_n = (it + 1) % STAGES;              // next-read stage
        if (it & 1) {
            if (it + 1 < cnt)
                load_frags(af0, bf0, sb + stage_n * STAGE_BYTES,
                           sb + stage_n * STAGE_BYTES + A_BYTES, mbase, lid);
            do_mmas(acc, af1, bf1);
        } else {
            if (it + 1 < cnt)
                load_frags(af1, bf1, sb + stage_n * STAGE_BYTES,
                           sb + stage_n * STAGE_BYTES + A_BYTES, mbase, lid);
            do_mmas(acc, af0, bf0);
        }
    }

    // Epilogue: D fragment layout -> global (zeros for empty rows).
    const int g = lid >> 2, t4 = lid & 3;
#pragma unroll
    for (int mi = 0; mi < 2; mi++) {
#pragma unroll
        for (int nj = 0; nj < 4; nj++) {
            const int row = batch0 + mbase + mi * 16 + g;
            const int col = r * BLOCK + nj * 8 + 2 * t4;
            float2* p0 = reinterpret_cast<float2*>(out + (size_t)row * OUT_FEAT + col);
            float2* p1 = reinterpret_cast<float2*>(out + (size_t)(row + 8) * OUT_FEAT + col);
            *p0 = make_float2(acc[mi][nj][0], acc[mi][nj][1]);
            *p1 = make_float2(acc[mi][nj][2], acc[mi][nj][3]);
        }
    }
}

// ---------------------------------------------------------------------------
// Launch
// ---------------------------------------------------------------------------
extern "C" void kernel_launch(void* const* d_in, const int* in_sizes, int n_in,
                              void* d_out, int out_size) {
    (void)in_sizes; (void)n_in; (void)out_size;
    const float* x    = (const float*)d_in[0];   // [2048, 4096] fp32
    const float* w    = (const float*)d_in[1];   // [2048, 32, 32] fp32
    const int*   rows = (const int*)d_in[2];     // [2048] int32
    const int*   cols = (const int*)d_in[3];     // [2048] int32
    float*       out  = (float*)d_out;           // [2048, 4096] fp32

    cudaFuncSetAttribute(bsd_main_kernel,
                         cudaFuncAttributeMaxDynamicSharedMemorySize, SMEM_DYN);

    cvt_kernel<<<X_F4_BLOCKS + W_F4_BLOCKS, 256>>>(x, w);
    csr_build_kernel<<<1, 128>>>(rows, cols);

    dim3 grid(N_ROW_BLOCKS, N_BATCH_TILES);
    bsd_main_kernel<<<grid, 128, SMEM_DYN>>>(out);
}

// round 6
// speedup vs baseline: 2.0594x; 2.0594x over previous
#include <cuda_runtime.h>
#include <cuda_fp16.h>
#include <cstdint>

// ---------------------------------------------------------------------------
// Problem constants
// ---------------------------------------------------------------------------
#define BATCH        2048
#define IN_FEAT      4096
#define OUT_FEAT     4096
#define BLOCK        32
#define NNZ          2048
#define N_ROW_BLOCKS 128
#define MTILE        128                    // batch rows per CTA
#define N_BATCH_TILES (BATCH / MTILE)       // 16

// ---------------------------------------------------------------------------
// Device scratch (__device__ globals only; no runtime allocation)
// ---------------------------------------------------------------------------
__device__ __align__(256) __half g_xh[BATCH * IN_FEAT];     // 16 MB
__device__ __align__(256) __half g_wh[NNZ * BLOCK * BLOCK]; // 4 MB
__device__ int g_cnt[N_ROW_BLOCKS];
__device__ int g_off[N_ROW_BLOCKS];
__device__ int g_order[N_ROW_BLOCKS];   // row-blocks sorted by cnt desc
__device__ int g_list[NNZ];             // packed: (col << 16) | nnz_index

// ---------------------------------------------------------------------------
// Helpers
// ---------------------------------------------------------------------------
__device__ __forceinline__ uint32_t smem_u32(const void* p) {
    uint32_t a;
    asm("{ .reg .u64 t; cvta.to.shared.u64 t, %1; cvt.u32.u64 %0, t; }"
        : "=r"(a) : "l"(p));
    return a;
}

// SW64 swizzle for 64B-pitch rows: XOR bits [5:4] with bits [9:8].
// Residual 2-way LDSM conflicts sit under the LDSM structural floor (4 cyc).
#define SW64(o) ((o) ^ (((o) >> 3) & 0x30))

#define CP_ASYNC16(dst, src) \
    asm volatile("cp.async.cg.shared.global [%0], [%1], 16;" \
                 :: "r"(dst), "l"(src) : "memory")
#define CP_COMMIT() asm volatile("cp.async.commit_group;" ::: "memory")
#define CP_WAIT1()  asm volatile("cp.async.wait_group 1;" ::: "memory")

__device__ __forceinline__ void ldsm_x4(uint32_t* r, uint32_t addr) {
    asm volatile("ldmatrix.sync.aligned.m8n8.x4.shared.b16 {%0,%1,%2,%3}, [%4];"
                 : "=r"(r[0]), "=r"(r[1]), "=r"(r[2]), "=r"(r[3])
                 : "r"(addr));
}

__device__ __forceinline__ void mma_16816(float* d, const uint32_t* a,
                                          const uint32_t* b) {
    asm volatile(
        "mma.sync.aligned.m16n8k16.row.col.f32.f16.f16.f32 "
        "{%0,%1,%2,%3}, {%4,%5,%6,%7}, {%8,%9}, {%0,%1,%2,%3};"
        : "+f"(d[0]), "+f"(d[1]), "+f"(d[2]), "+f"(d[3])
        : "r"(a[0]), "r"(a[1]), "r"(a[2]), "r"(a[3]), "r"(b[0]), "r"(b[1]));
}

// ---------------------------------------------------------------------------
// Kernel 1: fused fp32 -> fp16 conversion for x and w (ncu-verified healthy).
// ---------------------------------------------------------------------------
#define X_F4_BLOCKS 8192
#define W_F4_BLOCKS 2048

__global__ void __launch_bounds__(256) cvt_kernel(const float* __restrict__ x,
                                                  const float* __restrict__ w) {
    int b = blockIdx.x;
    if (b < X_F4_BLOCKS) {
        int i = b * 256 + threadIdx.x;
        float4 v = reinterpret_cast<const float4*>(x)[i];
        __half2* d = reinterpret_cast<__half2*>(g_xh);
        d[2 * i]     = __floats2half2_rn(v.x, v.y);
        d[2 * i + 1] = __floats2half2_rn(v.z, v.w);
    } else {
        int i = (b - X_F4_BLOCKS) * 256 + threadIdx.x;
        float4 v = reinterpret_cast<const float4*>(w)[i];
        __half2* d = reinterpret_cast<__half2*>(g_wh);
        d[2 * i]     = __floats2half2_rn(v.x, v.y);
        d[2 * i + 1] = __floats2half2_rn(v.z, v.w);
    }
}

// ---------------------------------------------------------------------------
// CSR build: R3's parallel ballot-based kernels (known good), order added
// to the prefix kernel (longest-first CTA schedule).
// ---------------------------------------------------------------------------
__global__ void csr_count_kernel(const int* __restrict__ rows) {
    int wid = (blockIdx.x * blockDim.x + threadIdx.x) >> 5;   // 0..127
    int lid = threadIdx.x & 31;
    int cnt = 0;
    for (int n0 = 0; n0 < NNZ; n0 += 32) {
        int v = rows[n0 + lid];
        unsigned m = __ballot_sync(0xffffffffu, v == wid);
        cnt += __popc(m);
    }
    if (lid == 0) g_cnt[wid] = cnt;
}

__global__ void __launch_bounds__(128) csr_prefix_kernel() {
    int r = threadIdx.x;           // 0..127
    __shared__ int s[N_ROW_BLOCKS];
    int cnt = g_cnt[r];
    s[r] = cnt;
    __syncthreads();
    int off = 0, rank = 0;
#pragma unroll 8
    for (int i = 0; i < N_ROW_BLOCKS; i++) {
        int ci = s[i];
        off  += (i < r) ? ci : 0;
        rank += (ci > cnt) || (ci == cnt && i < r);
    }
    g_off[r] = off;
    g_order[rank] = r;
}

__global__ void csr_scatter_kernel(const int* __restrict__ rows,
                                   const int* __restrict__ cols) {
    int wid = (blockIdx.x * blockDim.x + threadIdx.x) >> 5;   // row 0..127
    int lid = threadIdx.x & 31;
    int pos = g_off[wid];
    for (int n0 = 0; n0 < NNZ; n0 += 32) {
        int n = n0 + lid;
        int v = rows[n];
        unsigned m = __ballot_sync(0xffffffffu, v == wid);
        if (v == wid) {
            int p = pos + __popc(m & ((1u << lid) - 1));
            g_list[p] = (cols[n] << 16) | n;
        }
        pos += __popc(m);
    }
}

// ---------------------------------------------------------------------------
// Main block-sparse GEMM. Grid (128 row-blocks via g_order, 16 batch-tiles),
// 128 threads. 64B-pitch SW64 tiles (10KB/stage), 3 stages in 30KB static
// SMEM, ONE __syncthreads per iteration (refill targets the stage read at
// it-1, which the top barrier already protects). Single frag set, low regs.
// ---------------------------------------------------------------------------
#define A_BYTES     (MTILE * 64)           // 8192 per stage
#define B_BYTES     (BLOCK * 64)           // 2048 per stage
#define STAGE_BYTES (A_BYTES + B_BYTES)    // 10240
#define STAGES      3

__device__ __forceinline__ void issue_loads(uint32_t sA, uint32_t sB,
                                            int tid, int batch0, int packed) {
    const int c   = packed >> 16;
    const int idx = packed & 0xffff;
    const char* xs = reinterpret_cast<const char*>(
        g_xh + (size_t)(batch0 + tid) * IN_FEAT + c * BLOCK);
#pragma unroll
    for (int i = 0; i < 4; i++)
        CP_ASYNC16(sA + SW64((uint32_t)tid * 64 + i * 16), xs + i * 16);
    const int wr = tid >> 2, wi = tid & 3;
    const char* ws = reinterpret_cast<const char*>(
        g_wh + (size_t)idx * (BLOCK * BLOCK) + wr * BLOCK + wi * 8);
    CP_ASYNC16(sB + SW64((uint32_t)wr * 64 + wi * 16), ws);
}

__global__ void __launch_bounds__(128)
bsd_main_kernel(float* __restrict__ out) {
    __shared__ __align__(1024) char sbuf[STAGES * STAGE_BYTES];   // 30720 B

    const int r      = g_order[blockIdx.x];
    const int batch0 = blockIdx.y * MTILE;
    const int tid = threadIdx.x;
    const int wid = tid >> 5;
    const int lid = tid & 31;
    const int mbase = wid * 32;

    const uint32_t sb = smem_u32(sbuf);
    const int cnt = g_cnt[r];
    const int off = g_off[r];

    float acc[2][4][4];
#pragma unroll
    for (int mi = 0; mi < 2; mi++)
#pragma unroll
        for (int nj = 0; nj < 4; nj++)
#pragma unroll
            for (int k = 0; k < 4; k++) acc[mi][nj][k] = 0.f;

    // Prologue: issue blocks 0 and 1 into stages 0 and 1 (commit always).
    if (cnt > 0) issue_loads(sb, sb + A_BYTES, tid, batch0, g_list[off]);
    CP_COMMIT();
    if (cnt > 1) issue_loads(sb + STAGE_BYTES, sb + STAGE_BYTES + A_BYTES,
                             tid, batch0, g_list[off + 1]);
    CP_COMMIT();

    // Mainloop, one barrier per iteration:
    //  WAIT1  -> block `it` landed (groups pending: it, it+1)
    //  sync   -> cross-thread visibility of stage it%3 AND all reads of
    //            stage (it-1)%3 (done last iteration) complete
    //  issue block it+2 into stage (it+2)%3 == (it-1)%3  (just protected)
    //  ldmatrix + MMA on stage it%3
    for (int it = 0; it < cnt; ++it) {
        CP_WAIT1();
        __syncthreads();

        const int j = it + 2;
        const uint32_t sw = sb + ((uint32_t)(j % STAGES)) * STAGE_BYTES;
        if (j < cnt)
            issue_loads(sw, sw + A_BYTES, tid, batch0, g_list[off + j]);
        CP_COMMIT();

        const uint32_t sA = sb + ((uint32_t)(it % STAGES)) * STAGE_BYTES;
        const uint32_t sB = sA + A_BYTES;

        uint32_t af[2][2][4];
#pragma unroll
        for (int mi = 0; mi < 2; mi++)
#pragma unroll
            for (int ki = 0; ki < 2; ki++) {
                uint32_t row = (uint32_t)(mbase + mi * 16 + (lid & 15));
                uint32_t kb  = (uint32_t)(ki * 32 + ((lid >> 4) * 16));
                ldsm_x4(af[mi][ki], sA + SW64(row * 64 + kb));
            }
        uint32_t bf[2][4][2];
#pragma unroll
        for (int ki = 0; ki < 2; ki++)
#pragma unroll
            for (int p = 0; p < 2; p++) {
                uint32_t n  = (uint32_t)(p * 16 + ((lid >> 4) * 8) + (lid & 7));
                uint32_t kb = (uint32_t)(ki * 32 + (((lid >> 3) & 1) * 16));
                uint32_t t[4];
                ldsm_x4(t, sB + SW64(n * 64 + kb));
                bf[ki][2 * p + 0][0] = t[0];
                bf[ki][2 * p + 0][1] = t[1];
                bf[ki][2 * p + 1][0] = t[2];
                bf[ki][2 * p + 1][1] = t[3];
            }

#pragma unroll
        for (int mi = 0; mi < 2; mi++)
#pragma unroll
            for (int nj = 0; nj < 4; nj++)
#pragma unroll
                for (int ki = 0; ki < 2; ki++)
                    mma_16816(acc[mi][nj], af[mi][ki], bf[ki][nj]);
    }

    // Epilogue: D fragment layout -> global (zeros if row-block empty).
    const int g = lid >> 2, t4 = lid & 3;
#pragma unroll
    for (int mi = 0; mi < 2; mi++) {
#pragma unroll
        for (int nj = 0; nj < 4; nj++) {
            const int row = batch0 + mbase + mi * 16 + g;
            const int col = r * BLOCK + nj * 8 + 2 * t4;
            float2* p0 = reinterpret_cast<float2*>(out + (size_t)row * OUT_FEAT + col);
            float2* p1 = reinterpret_cast<float2*>(out + (size_t)(row + 8) * OUT_FEAT + col);
            *p0 = make_float2(acc[mi][nj][0], acc[mi][nj][1]);
            *p1 = make_float2(acc[mi][nj][2], acc[mi][nj][3]);
        }
    }
}

// ---------------------------------------------------------------------------
// Launch
// ---------------------------------------------------------------------------
extern "C" void kernel_launch(void* const* d_in, const int* in_sizes, int n_in,
                              void* d_out, int out_size) {
    (void)in_sizes; (void)n_in; (void)out_size;
    const float* x    = (const float*)d_in[0];   // [2048, 4096] fp32
    const float* w    = (const float*)d_in[1];   // [2048, 32, 32] fp32
    const int*   rows = (const int*)d_in[2];     // [2048] int32
    const int*   cols = (const int*)d_in[3];     // [2048] int32
    float*       out  = (float*)d_out;           // [2048, 4096] fp32

    cvt_kernel<<<X_F4_BLOCKS + W_F4_BLOCKS, 256>>>(x, w);
    csr_count_kernel<<<4, 1024>>>(rows);
    csr_prefix_kernel<<<1, 128>>>();
    csr_scatter_kernel<<<4, 1024>>>(rows, cols);

    dim3 grid(N_ROW_BLOCKS, N_BATCH_TILES);
    bsd_main_kernel<<<grid, 128>>>(out);
}

// round 7
// speedup vs baseline: 2.2544x; 1.0947x over previous
#include <cuda_runtime.h>
#include <cuda_fp16.h>
#include <cstdint>

// ---------------------------------------------------------------------------
// Problem constants
// ---------------------------------------------------------------------------
#define BATCH        2048
#define IN_FEAT      4096
#define OUT_FEAT     4096
#define BLOCK        32
#define NNZ          2048
#define N_ROW_BLOCKS 128
#define MTILE        128                    // batch rows per CTA
#define N_BATCH_TILES (BATCH / MTILE)       // 16
#define N_CHUNKS     (NNZ / 32)             // 64

// ---------------------------------------------------------------------------
// Device scratch (__device__ globals only; no runtime allocation)
// ---------------------------------------------------------------------------
__device__ __align__(256) __half g_xh[BATCH * IN_FEAT];     // 16 MB
__device__ __align__(256) __half g_wh[NNZ * BLOCK * BLOCK]; // 4 MB
__device__ int g_hist[N_CHUNKS * N_ROW_BLOCKS];   // per-chunk row histogram
__device__ int g_cnt[N_ROW_BLOCKS];
__device__ int g_off[N_ROW_BLOCKS];
__device__ int g_order[N_ROW_BLOCKS];   // row-blocks sorted by cnt desc
__device__ int g_list[NNZ];             // packed: (col << 16) | nnz_index

// ---------------------------------------------------------------------------
// Helpers
// ---------------------------------------------------------------------------
__device__ __forceinline__ uint32_t smem_u32(const void* p) {
    uint32_t a;
    asm("{ .reg .u64 t; cvta.to.shared.u64 t, %1; cvt.u32.u64 %0, t; }"
        : "=r"(a) : "l"(p));
    return a;
}

// SW64 swizzle for 64B-pitch rows: XOR bits [5:4] with bits [9:8].
#define SW64(o) ((o) ^ (((o) >> 3) & 0x30))

#define CP_ASYNC16(dst, src) \
    asm volatile("cp.async.cg.shared.global [%0], [%1], 16;" \
                 :: "r"(dst), "l"(src) : "memory")
#define CP_COMMIT() asm volatile("cp.async.commit_group;" ::: "memory")
#define CP_WAIT2()  asm volatile("cp.async.wait_group 2;" ::: "memory")

__device__ __forceinline__ void ldsm_x4(uint32_t* r, uint32_t addr) {
    asm volatile("ldmatrix.sync.aligned.m8n8.x4.shared.b16 {%0,%1,%2,%3}, [%4];"
                 : "=r"(r[0]), "=r"(r[1]), "=r"(r[2]), "=r"(r[3])
                 : "r"(addr));
}

__device__ __forceinline__ void mma_16816(float* d, const uint32_t* a,
                                          const uint32_t* b) {
    asm volatile(
        "mma.sync.aligned.m16n8k16.row.col.f32.f16.f16.f32 "
        "{%0,%1,%2,%3}, {%4,%5,%6,%7}, {%8,%9}, {%0,%1,%2,%3};"
        : "+f"(d[0]), "+f"(d[1]), "+f"(d[2]), "+f"(d[3])
        : "r"(a[0]), "r"(a[1]), "r"(a[2]), "r"(a[3]), "r"(b[0]), "r"(b[1]));
}

// ---------------------------------------------------------------------------
// Kernel 1: fused fp32->fp16 conversion (x, w) + per-chunk row histogram.
// Grid: 8192 x-blocks + 2048 w-blocks + 8 count-blocks, 256 threads.
// ---------------------------------------------------------------------------
#define X_F4_BLOCKS 8192
#define W_F4_BLOCKS 2048
#define CNT_BLOCKS  8      // 8 * 256 threads = 64 warps = 64 chunks

__global__ void __launch_bounds__(256)
cvt_count_kernel(const float* __restrict__ x, const float* __restrict__ w,
                 const int* __restrict__ rows) {
    int b = blockIdx.x;
    if (b < X_F4_BLOCKS) {
        int i = b * 256 + threadIdx.x;
        float4 v = reinterpret_cast<const float4*>(x)[i];
        __half2* d = reinterpret_cast<__half2*>(g_xh);
        d[2 * i]     = __floats2half2_rn(v.x, v.y);
        d[2 * i + 1] = __floats2half2_rn(v.z, v.w);
    } else if (b < X_F4_BLOCKS + W_F4_BLOCKS) {
        int i = (b - X_F4_BLOCKS) * 256 + threadIdx.x;
        float4 v = reinterpret_cast<const float4*>(w)[i];
        __half2* d = reinterpret_cast<__half2*>(g_wh);
        d[2 * i]     = __floats2half2_rn(v.x, v.y);
        d[2 * i + 1] = __floats2half2_rn(v.z, v.w);
    } else {
        // chunk histogram: warp c owns rows[c*32 .. c*32+31]
        int c   = (b - X_F4_BLOCKS - W_F4_BLOCKS) * 8 + (threadIdx.x >> 5);
        int lid = threadIdx.x & 31;
        // zero this chunk's 128-entry slice (4 per lane)
#pragma unroll
        for (int i = 0; i < 4; i++) g_hist[c * N_ROW_BLOCKS + lid * 4 + i] = 0;
        __syncwarp();
        int n = c * 32 + lid;
        int row = rows[n];
        unsigned m = __match_any_sync(0xffffffffu, row);
        int rank = __popc(m & ((1u << lid) - 1));
        if (rank == 0) g_hist[c * N_ROW_BLOCKS + row] = __popc(m);
    }
}

// ---------------------------------------------------------------------------
// Kernel 2: prefix (offsets + longest-first order) + radix scatter.
// One block, 1024 threads.
// ---------------------------------------------------------------------------
__global__ void __launch_bounds__(1024)
prefix_scatter_kernel(const int* __restrict__ rows, const int* __restrict__ cols) {
    __shared__ int s_total[N_ROW_BLOCKS];
    __shared__ int s_base[N_CHUNKS * N_ROW_BLOCKS];   // 32 KB
    const int t = threadIdx.x;

    if (t < N_ROW_BLOCKS) {
        int sum = 0;
#pragma unroll 8
        for (int c = 0; c < N_CHUNKS; c++) sum += g_hist[c * N_ROW_BLOCKS + t];
        s_total[t] = sum;
    }
    __syncthreads();

    if (t < N_ROW_BLOCKS) {
        const int cnt = s_total[t];
        int off = 0, rank = 0;
#pragma unroll 8
        for (int i = 0; i < N_ROW_BLOCKS; i++) {
            int ci = s_total[i];
            off  += (i < t) ? ci : 0;
            rank += (ci > cnt) || (ci == cnt && i < t);
        }
        g_cnt[t] = cnt;
        g_off[t] = off;
        g_order[rank] = t;
        int run = off;
#pragma unroll 8
        for (int c = 0; c < N_CHUNKS; c++) {
            s_base[c * N_ROW_BLOCKS + t] = run;
            run += g_hist[c * N_ROW_BLOCKS + t];
        }
    }
    __syncthreads();

    // scatter: 2048 elements, warp covers exactly one 32-chunk each pass
#pragma unroll
    for (int i = 0; i < 2; i++) {
        int n = i * 1024 + t;
        int row = rows[n];
        int chunk = n >> 5;
        int lid = t & 31;
        unsigned m = __match_any_sync(0xffffffffu, row);
        int rank = __popc(m & ((1u << lid) - 1));
        g_list[s_base[chunk * N_ROW_BLOCKS + row] + rank] = (cols[n] << 16) | n;
    }
}

// ---------------------------------------------------------------------------
// Kernel 3: main block-sparse GEMM.
// Grid (128 row-blocks via g_order, 16 batch-tiles), 128 threads.
// 64B-pitch SW64 tiles, 4 stages (40KB static SMEM), wait_group 2 → 3 blocks
// in flight, ONE __syncthreads per iteration (refill stage (it+3)%4 == stage
// read at it-1, protected by the top barrier).
// ---------------------------------------------------------------------------
#define A_BYTES     (MTILE * 64)           // 8192 per stage
#define B_BYTES     (BLOCK * 64)           // 2048 per stage
#define STAGE_BYTES (A_BYTES + B_BYTES)    // 10240
#define STAGES      4

__device__ __forceinline__ void issue_loads(uint32_t sA, uint32_t sB,
                                            int tid, int batch0, int packed) {
    const int c   = packed >> 16;
    const int idx = packed & 0xffff;
    const char* xs = reinterpret_cast<const char*>(
        g_xh + (size_t)(batch0 + tid) * IN_FEAT + c * BLOCK);
#pragma unroll
    for (int i = 0; i < 4; i++)
        CP_ASYNC16(sA + SW64((uint32_t)tid * 64 + i * 16), xs + i * 16);
    const int wr = tid >> 2, wi = tid & 3;
    const char* ws = reinterpret_cast<const char*>(
        g_wh + (size_t)idx * (BLOCK * BLOCK) + wr * BLOCK + wi * 8);
    CP_ASYNC16(sB + SW64((uint32_t)wr * 64 + wi * 16), ws);
}

__global__ void __launch_bounds__(128)
bsd_main_kernel(float* __restrict__ out) {
    __shared__ __align__(1024) char sbuf[STAGES * STAGE_BYTES];   // 40960 B

    const int r      = g_order[blockIdx.x];
    const int batch0 = blockIdx.y * MTILE;
    const int tid = threadIdx.x;
    const int wid = tid >> 5;
    const int lid = tid & 31;
    const int mbase = wid * 32;

    const uint32_t sb = smem_u32(sbuf);
    const int cnt = g_cnt[r];
    const int off = g_off[r];

    float acc[2][4][4];
#pragma unroll
    for (int mi = 0; mi < 2; mi++)
#pragma unroll
        for (int nj = 0; nj < 4; nj++)
#pragma unroll
            for (int k = 0; k < 4; k++) acc[mi][nj][k] = 0.f;

    // Prologue: issue blocks 0..2 into stages 0..2 (commit always).
#pragma unroll
    for (int s = 0; s < STAGES - 1; s++) {
        if (s < cnt)
            issue_loads(sb + s * STAGE_BYTES, sb + s * STAGE_BYTES + A_BYTES,
                        tid, batch0, g_list[off + s]);
        CP_COMMIT();
    }

    // Mainloop, one barrier per iteration:
    //  WAIT2  -> block `it` landed (≤2 groups pending after it)
    //  sync   -> visibility of stage it%4 + all reads of stage (it-1)%4 done
    //  issue block it+3 into stage (it+3)%4 == (it-1)%4
    //  ldmatrix + MMA on stage it%4
    for (int it = 0; it < cnt; ++it) {
        CP_WAIT2();
        __syncthreads();

        const int j = it + STAGES - 1;
        const uint32_t sw = sb + ((uint32_t)(j % STAGES)) * STAGE_BYTES;
        if (j < cnt)
            issue_loads(sw, sw + A_BYTES, tid, batch0, g_list[off + j]);
        CP_COMMIT();

        const uint32_t sA = sb + ((uint32_t)(it % STAGES)) * STAGE_BYTES;
        const uint32_t sB = sA + A_BYTES;

        uint32_t af[2][2][4];
#pragma unroll
        for (int mi = 0; mi < 2; mi++)
#pragma unroll
            for (int ki = 0; ki < 2; ki++) {
                uint32_t row = (uint32_t)(mbase + mi * 16 + (lid & 15));
                uint32_t kb  = (uint32_t)(ki * 32 + ((lid >> 4) * 16));
                ldsm_x4(af[mi][ki], sA + SW64(row * 64 + kb));
            }
        uint32_t bf[2][4][2];
#pragma unroll
        for (int ki = 0; ki < 2; ki++)
#pragma unroll
            for (int p = 0; p < 2; p++) {
                uint32_t n  = (uint32_t)(p * 16 + ((lid >> 4) * 8) + (lid & 7));
                uint32_t kb = (uint32_t)(ki * 32 + (((lid >> 3) & 1) * 16));
                uint32_t tt[4];
                ldsm_x4(tt, sB + SW64(n * 64 + kb));
                bf[ki][2 * p + 0][0] = tt[0];
                bf[ki][2 * p + 0][1] = tt[1];
                bf[ki][2 * p + 1][0] = tt[2];
                bf[ki][2 * p + 1][1] = tt[3];
            }

#pragma unroll
        for (int mi = 0; mi < 2; mi++)
#pragma unroll
            for (int nj = 0; nj < 4; nj++)
#pragma unroll
                for (int ki = 0; ki < 2; ki++)
                    mma_16816(acc[mi][nj], af[mi][ki], bf[ki][nj]);
    }

    // Epilogue: D fragment layout -> global (zeros if row-block empty).
    const int g = lid >> 2, t4 = lid & 3;
#pragma unroll
    for (int mi = 0; mi < 2; mi++) {
#pragma unroll
        for (int nj = 0; nj < 4; nj++) {
            const int row = batch0 + mbase + mi * 16 + g;
            const int col = r * BLOCK + nj * 8 + 2 * t4;
            float2* p0 = reinterpret_cast<float2*>(out + (size_t)row * OUT_FEAT + col);
            float2* p1 = reinterpret_cast<float2*>(out + (size_t)(row + 8) * OUT_FEAT + col);
            *p0 = make_float2(acc[mi][nj][0], acc[mi][nj][1]);
            *p1 = make_float2(acc[mi][nj][2], acc[mi][nj][3]);
        }
    }
}

// ---------------------------------------------------------------------------
// Launch (3 kernels; ncu -s 5 -c 1 lands on the main kernel of replay 1)
// ---------------------------------------------------------------------------
extern "C" void kernel_launch(void* const* d_in, const int* in_sizes, int n_in,
                              void* d_out, int out_size) {
    (void)in_sizes; (void)n_in; (void)out_size;
    const float* x    = (const float*)d_in[0];   // [2048, 4096] fp32
    const float* w    = (const float*)d_in[1];   // [2048, 32, 32] fp32
    const int*   rows = (const int*)d_in[2];     // [2048] int32
    const int*   cols = (const int*)d_in[3];     // [2048] int32
    float*       out  = (float*)d_out;           // [2048, 4096] fp32

    cvt_count_kernel<<<X_F4_BLOCKS + W_F4_BLOCKS + CNT_BLOCKS, 256>>>(x, w, rows);
    prefix_scatter_kernel<<<1, 1024>>>(rows, cols);

    dim3 grid(N_ROW_BLOCKS, N_BATCH_TILES);
    bsd_main_kernel<<<grid, 128>>>(out);
}